// round 1
// baseline (speedup 1.0000x reference)
#include <cuda_runtime.h>

// Problem constants
#define NWIN   4096   // B * NW windows
#define NTOK   49     // tokens per window
#define DIMC   96     // channels
#define HEADS  3
#define HD     32     // head dim
#define NWMASK 64     // windows per image (mask batch)

// smem layout (floats):
//  sx    [49*96]          = 4704   (reused as attention output before proj)
//  sw    [96*100]         = 9600   (weight tile, rows padded to 100 floats)
//  sq/sk/sv [3][49][32]   = 3*4704 = 14112
//  sattn [3][49][49]      = 7203   (bias+mask, then softmax probs)
#define SX_OFF    0
#define SW_OFF    4704
#define SQ_OFF    14304
#define SK_OFF    19008
#define SV_OFF    23712
#define SATTN_OFF 28416
#define SMEM_FLOATS 35619

__global__ __launch_bounds__(256, 1)
void win_attn_kernel(const float* __restrict__ x,
                     const float* __restrict__ mask,
                     const float* __restrict__ qkv_w,
                     const float* __restrict__ qkv_b,
                     const float* __restrict__ proj_w,
                     const float* __restrict__ proj_b,
                     const float* __restrict__ rpb,
                     const int*   __restrict__ rel_index,
                     float* __restrict__ out)
{
    extern __shared__ float sm[];
    float* sx    = sm + SX_OFF;
    float* sw    = sm + SW_OFF;
    float* sq    = sm + SQ_OFF;
    float* sk    = sm + SK_OFF;
    float* sv    = sm + SV_OFF;
    float* sattn = sm + SATTN_OFF;

    const int tid = threadIdx.x;
    const int bnw = blockIdx.x;
    const int w   = bnw & (NWMASK - 1);

    // ---- Stage 0: load x tile (float4) + precombine bias+mask into sattn ----
    {
        const float4* xg  = (const float4*)(x + (size_t)bnw * (NTOK * DIMC));
        float4*       sx4 = (float4*)sx;
        #pragma unroll 2
        for (int e = tid; e < (NTOK * DIMC) / 4; e += 256) sx4[e] = xg[e];

        #pragma unroll 2
        for (int e = tid; e < HEADS * NTOK * NTOK; e += 256) {
            int h = e / (NTOK * NTOK);
            int r = e - h * (NTOK * NTOK);     // i*49 + j
            sattn[e] = rpb[rel_index[r] * HEADS + h] + mask[w * (NTOK * NTOK) + r];
        }
    }
    __syncthreads();

    const int ty = tid >> 5;        // 0..7 -> rows ty*7 .. ty*7+6 (rows >=49 discarded)
    const int tx = tid & 31;        // 0..31 -> cols tx, tx+32, tx+64
    const int r0 = ty * 7;
    const float scale = 0.17677669529663687f;   // 32^-0.5

    const float4* sx4 = (const float4*)sx;

    // ---- Stage 1: qkv = x @ qkv_w^T + b  (three 96-col slices) ----
    for (int slice = 0; slice < 3; ++slice) {
        // stage weight slice: sw[row*100 + k] = qkv_w[slice*96+row][k]
        const float4* wg = (const float4*)(qkv_w + slice * 96 * 96);
        for (int e = tid; e < 96 * 24; e += 256) {
            int row = e / 24, c4 = e - row * 24;
            ((float4*)(sw + row * 100))[c4] = wg[e];
        }
        __syncthreads();

        float acc[7][3];
        #pragma unroll
        for (int u = 0; u < 7; u++)
            #pragma unroll
            for (int n = 0; n < 3; n++) acc[u][n] = 0.f;

        #pragma unroll
        for (int k4 = 0; k4 < 24; ++k4) {
            float4 a[7];
            #pragma unroll
            for (int u = 0; u < 7; u++) a[u] = sx4[(r0 + u) * 24 + k4];
            float4 b[3];
            #pragma unroll
            for (int n = 0; n < 3; n++)
                b[n] = *(const float4*)(sw + (tx + 32 * n) * 100 + k4 * 4);
            #pragma unroll
            for (int u = 0; u < 7; u++)
                #pragma unroll
                for (int n = 0; n < 3; n++) {
                    acc[u][n] = fmaf(a[u].x, b[n].x, acc[u][n]);
                    acc[u][n] = fmaf(a[u].y, b[n].y, acc[u][n]);
                    acc[u][n] = fmaf(a[u].z, b[n].z, acc[u][n]);
                    acc[u][n] = fmaf(a[u].w, b[n].w, acc[u][n]);
                }
        }

        float* dst = (slice == 0) ? sq : (slice == 1) ? sk : sv;
        const float mul = (slice == 0) ? scale : 1.f;
        #pragma unroll
        for (int n = 0; n < 3; n++) {
            int c = tx + 32 * n;
            float bias = qkv_b[slice * 96 + c];
            int h = c >> 5, d = c & 31;
            #pragma unroll
            for (int u = 0; u < 7; u++) {
                int rr = r0 + u;
                if (rr < NTOK) dst[h * (NTOK * HD) + rr * HD + d] = (acc[u][n] + bias) * mul;
            }
        }
        __syncthreads();
    }

    // ---- Stage 2: logits + sign-softmax (one thread per (head,row)) ----
    if (tid < HEADS * NTOK) {
        int h = tid / NTOK, i = tid - h * NTOK;
        const float4* qrow = (const float4*)(sq + h * (NTOK * HD) + i * HD);
        float4 qr[8];
        #pragma unroll
        for (int kk = 0; kk < 8; kk++) qr[kk] = qrow[kk];

        float* arow = sattn + h * (NTOK * NTOK) + i * NTOK;
        float l[NTOK];
        float mx = 0.f;
        #pragma unroll
        for (int j = 0; j < NTOK; j++) {
            const float4* krow = (const float4*)(sk + h * (NTOK * HD) + j * HD);
            float a = arow[j];   // bias + mask
            #pragma unroll
            for (int kk = 0; kk < 8; kk++) {
                float4 kv = krow[kk];
                a = fmaf(qr[kk].x, kv.x, a);
                a = fmaf(qr[kk].y, kv.y, a);
                a = fmaf(qr[kk].z, kv.z, a);
                a = fmaf(qr[kk].w, kv.w, a);
            }
            l[j] = a;
            mx = fmaxf(mx, fabsf(a));
        }
        float s = 0.f;
        #pragma unroll
        for (int j = 0; j < NTOK; j++) {
            float e = expf(fabsf(l[j]) - mx);
            s += e;
            l[j] = (l[j] > 0.f) ? e : ((l[j] < 0.f) ? -e : 0.f);
        }
        float inv = 1.f / s;
        #pragma unroll
        for (int j = 0; j < NTOK; j++) arow[j] = l[j] * inv;
    }
    __syncthreads();

    // ---- Stage 3: AV -> sao (reuse sx), layout (i, h*32+d) ----
    {
        float4* sao4 = (float4*)sx;
        for (int e = tid; e < (NTOK * DIMC) / 4; e += 256) {
            int i = e / 24, g = e - i * 24;     // g: float4 group within row (24 per row)
            int h  = g >> 3;                     // 8 groups per head
            int d4 = g & 7;
            const float*  prow  = sattn + h * (NTOK * NTOK) + i * NTOK;
            const float4* vbase = (const float4*)(sv + h * (NTOK * HD)) + d4;
            float4 acc = make_float4(0.f, 0.f, 0.f, 0.f);
            #pragma unroll
            for (int j = 0; j < NTOK; j++) {
                float  p  = prow[j];
                float4 vv = vbase[j * 8];
                acc.x = fmaf(p, vv.x, acc.x);
                acc.y = fmaf(p, vv.y, acc.y);
                acc.z = fmaf(p, vv.z, acc.z);
                acc.w = fmaf(p, vv.w, acc.w);
            }
            sao4[e] = acc;
        }
    }
    __syncthreads();

    // ---- Stage 4: out = sao @ proj_w^T + proj_b ----
    {
        const float4* wg = (const float4*)proj_w;
        for (int e = tid; e < 96 * 24; e += 256) {
            int row = e / 24, c4 = e - row * 24;
            ((float4*)(sw + row * 100))[c4] = wg[e];
        }
        __syncthreads();

        float acc[7][3];
        #pragma unroll
        for (int u = 0; u < 7; u++)
            #pragma unroll
            for (int n = 0; n < 3; n++) acc[u][n] = 0.f;

        #pragma unroll
        for (int k4 = 0; k4 < 24; ++k4) {
            float4 a[7];
            #pragma unroll
            for (int u = 0; u < 7; u++) a[u] = sx4[(r0 + u) * 24 + k4];
            float4 b[3];
            #pragma unroll
            for (int n = 0; n < 3; n++)
                b[n] = *(const float4*)(sw + (tx + 32 * n) * 100 + k4 * 4);
            #pragma unroll
            for (int u = 0; u < 7; u++)
                #pragma unroll
                for (int n = 0; n < 3; n++) {
                    acc[u][n] = fmaf(a[u].x, b[n].x, acc[u][n]);
                    acc[u][n] = fmaf(a[u].y, b[n].y, acc[u][n]);
                    acc[u][n] = fmaf(a[u].z, b[n].z, acc[u][n]);
                    acc[u][n] = fmaf(a[u].w, b[n].w, acc[u][n]);
                }
        }

        float* og = out + (size_t)bnw * (NTOK * DIMC);
        #pragma unroll
        for (int n = 0; n < 3; n++) {
            int c = tx + 32 * n;
            float pb = proj_b[c];
            #pragma unroll
            for (int u = 0; u < 7; u++) {
                int rr = r0 + u;
                if (rr < NTOK) og[rr * DIMC + c] = acc[u][n] + pb;
            }
        }
    }
}

extern "C" void kernel_launch(void* const* d_in, const int* in_sizes, int n_in,
                              void* d_out, int out_size) {
    const float* x      = (const float*)d_in[0];
    const float* mask   = (const float*)d_in[1];
    const float* qkv_w  = (const float*)d_in[2];
    const float* qkv_b  = (const float*)d_in[3];
    const float* proj_w = (const float*)d_in[4];
    const float* proj_b = (const float*)d_in[5];
    const float* rpb    = (const float*)d_in[6];
    const int*   relidx = (const int*)d_in[7];
    float* out = (float*)d_out;

    const int smem_bytes = SMEM_FLOATS * (int)sizeof(float);
    cudaFuncSetAttribute(win_attn_kernel,
                         cudaFuncAttributeMaxDynamicSharedMemorySize, smem_bytes);
    win_attn_kernel<<<NWIN, 256, smem_bytes>>>(x, mask, qkv_w, qkv_b,
                                               proj_w, proj_b, rpb, relidx, out);
}

// round 2
// speedup vs baseline: 1.2219x; 1.2219x over previous
#include <cuda_runtime.h>

typedef unsigned long long ull;

// Problem constants
#define NWIN   4096
#define NTOK   49
#define DIMC   96
#define HEADS  3
#define HD     32
#define NWMASK 64

// smem layout (floats) — sw and sattn OVERLAP (never live together):
//  sx   [49*96]  = 4704    @ 0      (x, later attention output O)
//  sq   [3*49*32]= 4704    @ 4704
//  sk             4704     @ 9408
//  sv             4704     @ 14112
//  swk  max(96*100, 3*49*49) = 9600 @ 18816   (weights OR bias+mask/probs)
#define SX_OFF  0
#define SQ_OFF  4704
#define SK_OFF  9408
#define SV_OFF  14112
#define SWK_OFF 18816
#define SMEM_FLOATS 28416   // 113664 bytes -> 2 blocks/SM

__device__ __forceinline__ ull pack2(float lo, float hi) {
    ull r; asm("mov.b64 %0, {%1,%2};" : "=l"(r) : "f"(lo), "f"(hi)); return r;
}
__device__ __forceinline__ float2 u2f(ull v) {
    float2 f; asm("mov.b64 {%0,%1}, %2;" : "=f"(f.x), "=f"(f.y) : "l"(v)); return f;
}
__device__ __forceinline__ ull fma2(ull a, ull b, ull c) {
    ull d; asm("fma.rn.f32x2 %0, %1, %2, %3;" : "=l"(d) : "l"(a), "l"(b), "l"(c)); return d;
}

// 49x96 @ 96x96^T GEMM micro-kernel, packed f32x2 along k.
// A rows are warp-uniform (broadcast LDS), B rows padded to 100 floats (conflict-free).
__device__ __forceinline__ void gemm_96(const float* __restrict__ sa,
                                        const float* __restrict__ swt,
                                        int r0, int tx, ull acc2[7][3])
{
    #pragma unroll
    for (int u = 0; u < 7; u++)
        #pragma unroll
        for (int n = 0; n < 3; n++) acc2[u][n] = 0ull;

    #pragma unroll
    for (int k4 = 0; k4 < 24; ++k4) {
        ulonglong2 a2[7];
        #pragma unroll
        for (int u = 0; u < 7; u++)
            a2[u] = *(const ulonglong2*)(sa + (r0 + u) * 96 + k4 * 4);
        ulonglong2 b2[3];
        #pragma unroll
        for (int n = 0; n < 3; n++)
            b2[n] = *(const ulonglong2*)(swt + (tx + 32 * n) * 100 + k4 * 4);
        #pragma unroll
        for (int u = 0; u < 7; u++)
            #pragma unroll
            for (int n = 0; n < 3; n++) {
                acc2[u][n] = fma2(a2[u].x, b2[n].x, acc2[u][n]);
                acc2[u][n] = fma2(a2[u].y, b2[n].y, acc2[u][n]);
            }
    }
}

__global__ __launch_bounds__(256, 2)
void win_attn_kernel(const float* __restrict__ x,
                     const float* __restrict__ mask,
                     const float* __restrict__ qkv_w,
                     const float* __restrict__ qkv_b,
                     const float* __restrict__ proj_w,
                     const float* __restrict__ proj_b,
                     const float* __restrict__ rpb,
                     const int*   __restrict__ rel_index,
                     float* __restrict__ out)
{
    extern __shared__ float sm[];
    float* sx  = sm + SX_OFF;
    float* sq  = sm + SQ_OFF;
    float* sk  = sm + SK_OFF;
    float* sv  = sm + SV_OFF;
    float* swk = sm + SWK_OFF;   // weights OR bias+mask/probs

    const int tid = threadIdx.x;
    const int bnw = blockIdx.x;
    const int w   = bnw & (NWMASK - 1);

    const int ty = tid >> 5;     // warp -> row group (rows ty*7..ty*7+6, >=49 discarded)
    const int tx = tid & 31;     // lane -> cols tx, tx+32, tx+64
    const int r0 = ty * 7;
    const float scale = 0.17677669529663687f;  // 32^-0.5

    // ---- Stage 0: load x tile ----
    {
        const float4* xg  = (const float4*)(x + (size_t)bnw * (NTOK * DIMC));
        float4* sx4 = (float4*)sx;
        #pragma unroll 2
        for (int e = tid; e < (NTOK * DIMC) / 4; e += 256) sx4[e] = xg[e];
    }
    __syncthreads();

    // ---- Stage 1: qkv GEMM (three 96-col slices), packed f32x2 ----
    for (int slice = 0; slice < 3; ++slice) {
        const float4* wg = (const float4*)(qkv_w + slice * 96 * 96);
        for (int e = tid; e < 96 * 24; e += 256) {
            int row = e / 24, c4 = e - row * 24;
            ((float4*)(swk + row * 100))[c4] = wg[e];
        }
        __syncthreads();

        ull acc2[7][3];
        gemm_96(sx, swk, r0, tx, acc2);

        float* dst = (slice == 0) ? sq : (slice == 1) ? sk : sv;
        const float mul = (slice == 0) ? scale : 1.f;
        #pragma unroll
        for (int n = 0; n < 3; n++) {
            int c = tx + 32 * n;
            float bias = qkv_b[slice * 96 + c];
            int h = c >> 5, d = c & 31;
            #pragma unroll
            for (int u = 0; u < 7; u++) {
                int rr = r0 + u;
                if (rr < NTOK) {
                    float2 f = u2f(acc2[u][n]);
                    dst[h * (NTOK * HD) + rr * HD + d] = (f.x + f.y + bias) * mul;
                }
            }
        }
        __syncthreads();
    }

    // ---- Stage 2a: fill swk with bias+mask (weight slab is dead now) ----
    #pragma unroll 2
    for (int e = tid; e < HEADS * NTOK * NTOK; e += 256) {
        int h = e / (NTOK * NTOK);
        int r = e - h * (NTOK * NTOK);
        swk[e] = rpb[rel_index[r] * HEADS + h] + mask[w * (NTOK * NTOK) + r];
    }
    __syncthreads();

    // ---- Stage 2b: logits + sign-softmax, in-place in smem (3 passes) ----
    if (tid < HEADS * NTOK) {
        int h = tid / NTOK, i = tid - h * NTOK;
        float* arow = swk + h * (NTOK * NTOK) + i * NTOK;
        const ulonglong2* q2 = (const ulonglong2*)(sq + h * (NTOK * HD) + i * HD);
        ulonglong2 qp[8];
        #pragma unroll
        for (int t = 0; t < 8; t++) qp[t] = q2[t];

        float mx = 0.f;
        for (int j = 0; j < NTOK; j++) {
            const ulonglong2* k2 = (const ulonglong2*)(sk + h * (NTOK * HD) + j * HD);
            ull acc = pack2(arow[j], 0.f);
            #pragma unroll
            for (int t = 0; t < 8; t++) {
                ulonglong2 kv = k2[t];
                acc = fma2(qp[t].x, kv.x, acc);
                acc = fma2(qp[t].y, kv.y, acc);
            }
            float2 f = u2f(acc);
            float a = f.x + f.y;
            arow[j] = a;
            mx = fmaxf(mx, fabsf(a));
        }
        float s = 0.f;
        for (int j = 0; j < NTOK; j++) {
            float a = arow[j];
            float e = __expf(fabsf(a) - mx);
            s += e;
            arow[j] = (a > 0.f) ? e : ((a < 0.f) ? -e : 0.f);
        }
        float inv = 1.f / s;
        for (int j = 0; j < NTOK; j++) arow[j] *= inv;
    }
    __syncthreads();

    // ---- Stage 3: AV -> O into sx (x is dead), packed f32x2 ----
    {
        float4* sao4 = (float4*)sx;
        for (int e = tid; e < (NTOK * DIMC) / 4; e += 256) {
            int i = e / 24, g = e - i * 24;
            int h = g >> 3, d4 = g & 7;
            const float* prow = swk + h * (NTOK * NTOK) + i * NTOK;
            const ulonglong2* vb = (const ulonglong2*)(sv + h * (NTOK * HD)) + d4 * 2;
            // note: row j of head block = 32 floats = 2x ulonglong2... d4 indexes float4:
            // float4 idx = j*8 + d4  ->  ulonglong2 pair at (j*8 + d4)
            ull acc0 = 0ull, acc1 = 0ull;
            for (int j = 0; j < NTOK; j++) {
                float p = prow[j];
                ull pp = pack2(p, p);
                const ulonglong2* vv4 = (const ulonglong2*)(sv + h * (NTOK * HD) + j * HD + d4 * 4);
                ulonglong2 vv = *vv4;
                acc0 = fma2(pp, vv.x, acc0);
                acc1 = fma2(pp, vv.y, acc1);
            }
            float2 lo = u2f(acc0), hi = u2f(acc1);
            sao4[e] = make_float4(lo.x, lo.y, hi.x, hi.y);
            (void)vb;
        }
    }
    __syncthreads();

    // ---- Stage 4: projection GEMM (weights overwrite probs — dead) ----
    {
        const float4* wg = (const float4*)proj_w;
        for (int e = tid; e < 96 * 24; e += 256) {
            int row = e / 24, c4 = e - row * 24;
            ((float4*)(swk + row * 100))[c4] = wg[e];
        }
        __syncthreads();

        ull acc2[7][3];
        gemm_96(sx, swk, r0, tx, acc2);

        float* og = out + (size_t)bnw * (NTOK * DIMC);
        #pragma unroll
        for (int n = 0; n < 3; n++) {
            int c = tx + 32 * n;
            float pb = proj_b[c];
            #pragma unroll
            for (int u = 0; u < 7; u++) {
                int rr = r0 + u;
                if (rr < NTOK) {
                    float2 f = u2f(acc2[u][n]);
                    og[rr * DIMC + c] = f.x + f.y + pb;
                }
            }
        }
    }
}

extern "C" void kernel_launch(void* const* d_in, const int* in_sizes, int n_in,
                              void* d_out, int out_size) {
    const float* x      = (const float*)d_in[0];
    const float* mask   = (const float*)d_in[1];
    const float* qkv_w  = (const float*)d_in[2];
    const float* qkv_b  = (const float*)d_in[3];
    const float* proj_w = (const float*)d_in[4];
    const float* proj_b = (const float*)d_in[5];
    const float* rpb    = (const float*)d_in[6];
    const int*   relidx = (const int*)d_in[7];
    float* out = (float*)d_out;

    const int smem_bytes = SMEM_FLOATS * (int)sizeof(float);
    cudaFuncSetAttribute(win_attn_kernel,
                         cudaFuncAttributeMaxDynamicSharedMemorySize, smem_bytes);
    win_attn_kernel<<<NWIN, 256, smem_bytes>>>(x, mask, qkv_w, qkv_b,
                                               proj_w, proj_b, rpb, relidx, out);
}

// round 3
// speedup vs baseline: 1.2587x; 1.0301x over previous
#include <cuda_runtime.h>

typedef unsigned long long ull;

#define NWIN   4096
#define NTOK   49
#define DIMC   96
#define HEADS  3
#define HD     32
#define NWMASK 64

// smem layout (floats) — sw and sattn OVERLAP (never live together):
//  sx   [49*96]  = 4704    @ 0      (x, later attention output O)
//  sq   [3*49*32]= 4704    @ 4704
//  sk             4704     @ 9408
//  sv             4704     @ 14112
//  swk  max(96*100, 3*49*49) = 9600 @ 18816   (weights OR probs; tail = sinv)
#define SX_OFF  0
#define SQ_OFF  4704
#define SK_OFF  9408
#define SV_OFF  14112
#define SWK_OFF 18816
#define SINV_OFF (SWK_OFF + 7296)   // 147 floats in swk tail (free during softmax/AV)
#define SMEM_FLOATS 28416           // 113664 B -> 2 blocks/SM

__device__ __forceinline__ ull pack2(float lo, float hi) {
    ull r; asm("mov.b64 %0, {%1,%2};" : "=l"(r) : "f"(lo), "f"(hi)); return r;
}
__device__ __forceinline__ float2 u2f(ull v) {
    float2 f; asm("mov.b64 {%0,%1}, %2;" : "=f"(f.x), "=f"(f.y) : "l"(v)); return f;
}
__device__ __forceinline__ ull fma2(ull a, ull b, ull c) {
    ull d; asm("fma.rn.f32x2 %0, %1, %2, %3;" : "=l"(d) : "l"(a), "l"(b), "l"(c)); return d;
}
__device__ __forceinline__ ull add2(ull a, ull b) {
    ull d; asm("add.rn.f32x2 %0, %1, %2;" : "=l"(d) : "l"(a), "l"(b)); return d;
}

// 49x96 @ 96x96^T GEMM micro-kernel, packed f32x2 along k.
__device__ __forceinline__ void gemm_96(const float* __restrict__ sa,
                                        const float* __restrict__ swt,
                                        int r0, int tx, ull acc2[7][3])
{
    #pragma unroll
    for (int u = 0; u < 7; u++)
        #pragma unroll
        for (int n = 0; n < 3; n++) acc2[u][n] = 0ull;

    #pragma unroll
    for (int k4 = 0; k4 < 24; ++k4) {
        ulonglong2 a2[7];
        #pragma unroll
        for (int u = 0; u < 7; u++)
            a2[u] = *(const ulonglong2*)(sa + (r0 + u) * 96 + k4 * 4);
        ulonglong2 b2[3];
        #pragma unroll
        for (int n = 0; n < 3; n++)
            b2[n] = *(const ulonglong2*)(swt + (tx + 32 * n) * 100 + k4 * 4);
        #pragma unroll
        for (int u = 0; u < 7; u++)
            #pragma unroll
            for (int n = 0; n < 3; n++) {
                acc2[u][n] = fma2(a2[u].x, b2[n].x, acc2[u][n]);
                acc2[u][n] = fma2(a2[u].y, b2[n].y, acc2[u][n]);
            }
    }
}

__global__ __launch_bounds__(256, 2)
void win_attn_kernel(const float* __restrict__ x,
                     const float* __restrict__ mask,
                     const float* __restrict__ qkv_w,
                     const float* __restrict__ qkv_b,
                     const float* __restrict__ proj_w,
                     const float* __restrict__ proj_b,
                     const float* __restrict__ rpb,
                     const int*   __restrict__ rel_index,
                     float* __restrict__ out)
{
    extern __shared__ float sm[];
    float* sx   = sm + SX_OFF;
    float* sq   = sm + SQ_OFF;
    float* sk   = sm + SK_OFF;
    float* sv   = sm + SV_OFF;
    float* swk  = sm + SWK_OFF;
    float* sinv = sm + SINV_OFF;

    const int tid = threadIdx.x;
    const int bnw = blockIdx.x;
    const int w   = bnw & (NWMASK - 1);

    const int ty = tid >> 5;
    const int tx = tid & 31;
    const int r0 = ty * 7;
    const float scale = 0.17677669529663687f;  // 32^-0.5

    // ---- Stage 0: load x tile ----
    {
        const float4* xg  = (const float4*)(x + (size_t)bnw * (NTOK * DIMC));
        float4* sx4 = (float4*)sx;
        #pragma unroll 2
        for (int e = tid; e < (NTOK * DIMC) / 4; e += 256) sx4[e] = xg[e];
    }
    __syncthreads();

    // ---- Stage 1: qkv GEMM (three 96-col slices), packed f32x2 ----
    for (int slice = 0; slice < 3; ++slice) {
        const float4* wg = (const float4*)(qkv_w + slice * 96 * 96);
        for (int e = tid; e < 96 * 24; e += 256) {
            int row = e / 24, c4 = e - row * 24;
            ((float4*)(swk + row * 100))[c4] = wg[e];
        }
        __syncthreads();

        ull acc2[7][3];
        gemm_96(sx, swk, r0, tx, acc2);

        float* dst = (slice == 0) ? sq : (slice == 1) ? sk : sv;
        const float mul = (slice == 0) ? scale : 1.f;
        #pragma unroll
        for (int n = 0; n < 3; n++) {
            int c = tx + 32 * n;
            float bias = qkv_b[slice * 96 + c];
            int h = c >> 5, d = c & 31;
            #pragma unroll
            for (int u = 0; u < 7; u++) {
                int rr = r0 + u;
                if (rr < NTOK) {
                    float2 f = u2f(acc2[u][n]);
                    dst[h * (NTOK * HD) + rr * HD + d] = (f.x + f.y + bias) * mul;
                }
            }
        }
        __syncthreads();
    }

    // ---- Stage 2: logits (bias+mask via LDG) + sign-softmax ----
    if (tid < HEADS * NTOK) {
        const int h = tid / NTOK;
        const int i = tid - h * NTOK;
        const ulonglong2* q2 = (const ulonglong2*)(sq + h * (NTOK * HD) + i * HD);
        ulonglong2 qp[8];
        #pragma unroll
        for (int t = 0; t < 8; t++) qp[t] = q2[t];

        float* arow = swk + h * (NTOK * NTOK) + i * NTOK;
        const float* mrow = mask + w * (NTOK * NTOK) + i * NTOK;
        const int*   rrow = rel_index + i * NTOK;
        const float* kbase = sk + h * (NTOK * HD);

        float mx0 = 0.f, mx1 = 0.f;
        #pragma unroll 7
        for (int j = 0; j < NTOK; j++) {
            float bm = __ldg(&rpb[__ldg(&rrow[j]) * HEADS + h]) + __ldg(&mrow[j]);
            const ulonglong2* k2 = (const ulonglong2*)(kbase + j * HD);
            ull a0 = 0ull, a1 = 0ull, a2 = 0ull, a3 = 0ull;
            #pragma unroll
            for (int t = 0; t < 8; t += 2) {
                ulonglong2 kva = k2[t];
                ulonglong2 kvb = k2[t + 1];
                a0 = fma2(qp[t].x,     kva.x, a0);
                a1 = fma2(qp[t].y,     kva.y, a1);
                a2 = fma2(qp[t + 1].x, kvb.x, a2);
                a3 = fma2(qp[t + 1].y, kvb.y, a3);
            }
            float2 f = u2f(add2(add2(a0, a1), add2(a2, a3)));
            float a = f.x + f.y + bm;
            arow[j] = a;
            if (j & 1) mx1 = fmaxf(mx1, fabsf(a));
            else       mx0 = fmaxf(mx0, fabsf(a));
        }
        float mx = fmaxf(mx0, mx1);

        float s0 = 0.f, s1 = 0.f;
        #pragma unroll 7
        for (int j = 0; j < NTOK; j++) {
            float a = arow[j];
            float e = __expf(fabsf(a) - mx);
            if (j & 1) s1 += e;
            else       s0 += e;
            arow[j] = (a > 0.f) ? e : ((a < 0.f) ? -e : 0.f);
        }
        sinv[tid] = 1.f / (s0 + s1);
    }
    __syncthreads();

    // ---- Stage 3: AV -> O into sx (x is dead), scale by 1/s at the end ----
    {
        float4* sao4 = (float4*)sx;
        #pragma unroll 2
        for (int e = tid; e < (NTOK * DIMC) / 4; e += 256) {
            int i = e / 24, g = e - i * 24;
            int h = g >> 3, d4 = g & 7;
            const float* prow  = swk + h * (NTOK * NTOK) + i * NTOK;
            const float* vbase = sv + h * (NTOK * HD) + d4 * 4;
            ull acc0 = 0ull, acc1 = 0ull, acc2 = 0ull, acc3 = 0ull;
            #pragma unroll
            for (int j = 0; j < NTOK - 1; j += 2) {
                float p0 = prow[j], p1 = prow[j + 1];
                ulonglong2 v0 = *(const ulonglong2*)(vbase + j * HD);
                ulonglong2 v1 = *(const ulonglong2*)(vbase + (j + 1) * HD);
                ull pp0 = pack2(p0, p0), pp1 = pack2(p1, p1);
                acc0 = fma2(pp0, v0.x, acc0);
                acc1 = fma2(pp0, v0.y, acc1);
                acc2 = fma2(pp1, v1.x, acc2);
                acc3 = fma2(pp1, v1.y, acc3);
            }
            {   // peel j = 48
                float p = prow[NTOK - 1];
                ulonglong2 vv = *(const ulonglong2*)(vbase + (NTOK - 1) * HD);
                ull pp = pack2(p, p);
                acc0 = fma2(pp, vv.x, acc0);
                acc1 = fma2(pp, vv.y, acc1);
            }
            float inv = sinv[h * NTOK + i];
            float2 lo = u2f(add2(acc0, acc2));
            float2 hi = u2f(add2(acc1, acc3));
            sao4[e] = make_float4(lo.x * inv, lo.y * inv, hi.x * inv, hi.y * inv);
        }
    }
    __syncthreads();

    // ---- Stage 4: projection GEMM (weights overwrite probs — dead) ----
    {
        const float4* wg = (const float4*)proj_w;
        for (int e = tid; e < 96 * 24; e += 256) {
            int row = e / 24, c4 = e - row * 24;
            ((float4*)(swk + row * 100))[c4] = wg[e];
        }
        __syncthreads();

        ull acc2[7][3];
        gemm_96(sx, swk, r0, tx, acc2);

        float* og = out + (size_t)bnw * (NTOK * DIMC);
        #pragma unroll
        for (int n = 0; n < 3; n++) {
            int c = tx + 32 * n;
            float pb = proj_b[c];
            #pragma unroll
            for (int u = 0; u < 7; u++) {
                int rr = r0 + u;
                if (rr < NTOK) {
                    float2 f = u2f(acc2[u][n]);
                    og[rr * DIMC + c] = f.x + f.y + pb;
                }
            }
        }
    }
}

extern "C" void kernel_launch(void* const* d_in, const int* in_sizes, int n_in,
                              void* d_out, int out_size) {
    const float* x      = (const float*)d_in[0];
    const float* mask   = (const float*)d_in[1];
    const float* qkv_w  = (const float*)d_in[2];
    const float* qkv_b  = (const float*)d_in[3];
    const float* proj_w = (const float*)d_in[4];
    const float* proj_b = (const float*)d_in[5];
    const float* rpb    = (const float*)d_in[6];
    const int*   relidx = (const int*)d_in[7];
    float* out = (float*)d_out;

    const int smem_bytes = SMEM_FLOATS * (int)sizeof(float);
    cudaFuncSetAttribute(win_attn_kernel,
                         cudaFuncAttributeMaxDynamicSharedMemorySize, smem_bytes);
    win_attn_kernel<<<NWIN, 256, smem_bytes>>>(x, mask, qkv_w, qkv_b,
                                               proj_w, proj_b, rpb, relidx, out);
}